// round 1
// baseline (speedup 1.0000x reference)
#include <cuda_runtime.h>
#include <cuda_bf16.h>
#include <stdint.h>

// Problem dims (from reference setup_inputs)
#define MAX_N 100000
#define MAX_E 1600000
#define IN_DIM 128
#define HID 64
#define LAT 32

// ---------------- device scratch (no allocations allowed) ----------------
__device__ float g_deg[MAX_N];
__device__ float g_dinv[MAX_N];
__device__ int   g_cnt[MAX_N];
__device__ int   g_rowptr[MAX_N];
__device__ int   g_cursor[MAX_N];
__device__ int   g_col[MAX_E];
__device__ float g_val[MAX_E];
__device__ float g_xw[(size_t)MAX_N * HID];
__device__ float g_h[(size_t)MAX_N * HID];
__device__ float g_h2[(size_t)MAX_N * HID];
__device__ int   g_bsum[256];
__device__ int   g_boff[256];
__device__ int   g_is64;

// ---------------- dtype detection for edge_index ----------------
// jnp asks for int64 but default JAX config downgrades to int32. Detect at
// runtime: if stored as int64 (values < 2^31, nonnegative), every odd 32-bit
// word is 0. With int32 data those words are random node ids.
__global__ void k_detect(const int* ei32) {
    if (blockIdx.x == 0 && threadIdx.x == 0) {
        int is64 = 1;
        for (int i = 0; i < 256; i++) {
            if (ei32[2 * i + 1] != 0) { is64 = 0; break; }
        }
        g_is64 = is64;
    }
}

__device__ __forceinline__ int get_idx(const void* ei, long long pos) {
    if (g_is64) return (int)((const long long*)ei)[pos];
    return ((const int*)ei)[pos];
}

// ---------------- degree / CSR build ----------------
__global__ void k_init(int n) {
    int i = blockIdx.x * blockDim.x + threadIdx.x;
    if (i < n) { g_deg[i] = 1.0f; g_cnt[i] = 0; g_cursor[i] = 0; }
}

__global__ void k_count(const void* ei, const float* __restrict__ ew, int E) {
    int e = blockIdx.x * blockDim.x + threadIdx.x;
    if (e < E) {
        int d = get_idx(ei, (long long)E + e);
        atomicAdd(&g_deg[d], ew[e]);
        atomicAdd(&g_cnt[d], 1);
    }
}

__global__ void k_dinv(int n) {
    int i = blockIdx.x * blockDim.x + threadIdx.x;
    if (i < n) g_dinv[i] = rsqrtf(g_deg[i]);
}

// 3-kernel exclusive scan of g_cnt -> g_rowptr
__global__ void k_scan1(int n) {
    __shared__ int sh[1024];
    int i = blockIdx.x * 1024 + threadIdx.x;
    int v = (i < n) ? g_cnt[i] : 0;
    sh[threadIdx.x] = v;
    __syncthreads();
    for (int off = 1; off < 1024; off <<= 1) {
        int t = (threadIdx.x >= off) ? sh[threadIdx.x - off] : 0;
        __syncthreads();
        sh[threadIdx.x] += t;
        __syncthreads();
    }
    if (i < n) g_rowptr[i] = sh[threadIdx.x];  // inclusive for now
    if (threadIdx.x == 1023) g_bsum[blockIdx.x] = sh[1023];
}

__global__ void k_scan2(int nb) {
    if (threadIdx.x == 0 && blockIdx.x == 0) {
        int acc = 0;
        for (int b = 0; b < nb; b++) { int t = g_bsum[b]; g_boff[b] = acc; acc += t; }
    }
}

__global__ void k_scan3(int n) {
    int i = blockIdx.x * blockDim.x + threadIdx.x;
    if (i < n) g_rowptr[i] = g_rowptr[i] - g_cnt[i] + g_boff[i >> 10];
}

__global__ void k_fill(const void* ei, const float* __restrict__ ew, int E) {
    int e = blockIdx.x * blockDim.x + threadIdx.x;
    if (e < E) {
        int s = get_idx(ei, e);
        int d = get_idx(ei, (long long)E + e);
        int pos = g_rowptr[d] + atomicAdd(&g_cursor[d], 1);
        g_col[pos] = s;
        g_val[pos] = g_dinv[s] * ew[e] * g_dinv[d];
    }
}

// ---------------- propagation: out[i] = dinv[i]^2*in[i] + sum_e val*in[src] ----
// warp per dst node, 2 dims per lane. Gather is coalesced 128B rows; h fits L2.
__global__ void k_prop(const float* __restrict__ in, float* __restrict__ out,
                       const float* __restrict__ bias, int relu, int n) {
    int w = (blockIdx.x * blockDim.x + threadIdx.x) >> 5;
    int lane = threadIdx.x & 31;
    if (w >= n) return;
    float di = g_dinv[w];
    float wself = di * di;
    const float* r = in + (size_t)w * HID;
    float a0 = wself * r[lane];
    float a1 = wself * r[lane + 32];
    int s = g_rowptr[w];
    int e = s + g_cnt[w];
    for (int j = s; j < e; j++) {
        int c = g_col[j];
        float v = g_val[j];
        const float* rs = in + (size_t)c * HID;
        a0 += v * rs[lane];
        a1 += v * rs[lane + 32];
    }
    if (bias) { a0 += bias[lane]; a1 += bias[lane + 32]; }
    if (relu) { a0 = fmaxf(a0, 0.0f); a1 = fmaxf(a1, 0.0f); }
    out[(size_t)w * HID + lane] = a0;
    out[(size_t)w * HID + lane + 32] = a1;
}

// ---------------- GEMM1: C[M,64] = A[M,128] @ W[128,64] ----------------
// 64-row blocks, 256 threads, 4x4 micro-tiles, float4 smem loads.
__global__ void k_gemm1(const float* __restrict__ A, const float* __restrict__ W,
                        float* __restrict__ C, int M) {
    __shared__ float Bs[IN_DIM * HID];   // 32KB: full W
    __shared__ float Ast[64 * 64];       // 16KB: K-half of A, transposed [k][row]
    int tid = threadIdx.x;
    int row0 = blockIdx.x * 64;

    const float4* W4 = (const float4*)W;
    float4* Bs4 = (float4*)Bs;
    for (int t = tid; t < IN_DIM * HID / 4; t += 256) Bs4[t] = W4[t];

    int tx = tid % 16, ty = tid / 16;
    float acc[4][4] = {};

    const float4* A4 = (const float4*)A;
    for (int kh = 0; kh < 2; kh++) {
        __syncthreads();
        // load 64 rows x 64 ks transposed
        for (int idx = tid; idx < 64 * 16; idx += 256) {
            int r = idx % 64;
            int k4 = idx / 64;  // 0..15
            int gr = row0 + r;
            float4 a = (gr < M) ? A4[(size_t)gr * 32 + kh * 16 + k4]
                                : make_float4(0.f, 0.f, 0.f, 0.f);
            Ast[(4 * k4 + 0) * 64 + r] = a.x;
            Ast[(4 * k4 + 1) * 64 + r] = a.y;
            Ast[(4 * k4 + 2) * 64 + r] = a.z;
            Ast[(4 * k4 + 3) * 64 + r] = a.w;
        }
        __syncthreads();
#pragma unroll 8
        for (int k = 0; k < 64; k++) {
            float4 av = *(const float4*)(Ast + k * 64 + 4 * ty);
            float4 bv = *(const float4*)(Bs + (kh * 64 + k) * 64 + 4 * tx);
            acc[0][0] += av.x * bv.x; acc[0][1] += av.x * bv.y; acc[0][2] += av.x * bv.z; acc[0][3] += av.x * bv.w;
            acc[1][0] += av.y * bv.x; acc[1][1] += av.y * bv.y; acc[1][2] += av.y * bv.z; acc[1][3] += av.y * bv.w;
            acc[2][0] += av.z * bv.x; acc[2][1] += av.z * bv.y; acc[2][2] += av.z * bv.z; acc[2][3] += av.z * bv.w;
            acc[3][0] += av.w * bv.x; acc[3][1] += av.w * bv.y; acc[3][2] += av.w * bv.z; acc[3][3] += av.w * bv.w;
        }
    }
#pragma unroll
    for (int i = 0; i < 4; i++) {
        int gr = row0 + 4 * ty + i;
        if (gr < M) {
            float4 o = make_float4(acc[i][0], acc[i][1], acc[i][2], acc[i][3]);
            ((float4*)C)[(size_t)gr * 16 + tx] = o;
        }
    }
}

// ---------------- GEMM2: [mu|lv] = h2[M,64] @ [Wmu|Wlv][64,64] + bias ------
__global__ void k_gemm2(const float* __restrict__ A,
                        const float* __restrict__ Wmu, const float* __restrict__ Wlv,
                        const float* __restrict__ bmu, const float* __restrict__ blv,
                        float* __restrict__ Omu, float* __restrict__ Olv, int M) {
    __shared__ float Bs[HID * HID];   // 16KB
    __shared__ float Ast[64 * 64];    // 16KB
    int tid = threadIdx.x;
    int row0 = blockIdx.x * 64;

    // assemble B = [Wmu | Wlv] : Bs[k][c]
    {
        const float4* Wm4 = (const float4*)Wmu;
        const float4* Wl4 = (const float4*)Wlv;
        float4* Bs4 = (float4*)Bs;
        for (int t = tid; t < HID * HID / 4; t += 256) {
            int k = t / 16;   // 16 float4 per row of 64
            int c4 = t % 16;
            Bs4[t] = (c4 < 8) ? Wm4[k * 8 + c4] : Wl4[k * 8 + (c4 - 8)];
        }
    }
    // load A transposed
    const float4* A4 = (const float4*)A;
    for (int idx = tid; idx < 64 * 16; idx += 256) {
        int r = idx % 64;
        int k4 = idx / 64;
        int gr = row0 + r;
        float4 a = (gr < M) ? A4[(size_t)gr * 16 + k4] : make_float4(0.f, 0.f, 0.f, 0.f);
        Ast[(4 * k4 + 0) * 64 + r] = a.x;
        Ast[(4 * k4 + 1) * 64 + r] = a.y;
        Ast[(4 * k4 + 2) * 64 + r] = a.z;
        Ast[(4 * k4 + 3) * 64 + r] = a.w;
    }
    __syncthreads();

    int tx = tid % 16, ty = tid / 16;
    float acc[4][4] = {};
#pragma unroll 8
    for (int k = 0; k < 64; k++) {
        float4 av = *(const float4*)(Ast + k * 64 + 4 * ty);
        float4 bv = *(const float4*)(Bs + k * 64 + 4 * tx);
        acc[0][0] += av.x * bv.x; acc[0][1] += av.x * bv.y; acc[0][2] += av.x * bv.z; acc[0][3] += av.x * bv.w;
        acc[1][0] += av.y * bv.x; acc[1][1] += av.y * bv.y; acc[1][2] += av.y * bv.z; acc[1][3] += av.y * bv.w;
        acc[2][0] += av.z * bv.x; acc[2][1] += av.z * bv.y; acc[2][2] += av.z * bv.z; acc[2][3] += av.z * bv.w;
        acc[3][0] += av.w * bv.x; acc[3][1] += av.w * bv.y; acc[3][2] += av.w * bv.z; acc[3][3] += av.w * bv.w;
    }

    if (tx < 8) {
        float4 bb = ((const float4*)bmu)[tx];
#pragma unroll
        for (int i = 0; i < 4; i++) {
            int gr = row0 + 4 * ty + i;
            if (gr < M) {
                float4 o = make_float4(acc[i][0] + bb.x, acc[i][1] + bb.y,
                                       acc[i][2] + bb.z, acc[i][3] + bb.w);
                ((float4*)Omu)[(size_t)gr * 8 + tx] = o;
            }
        }
    } else {
        float4 bb = ((const float4*)blv)[tx - 8];
#pragma unroll
        for (int i = 0; i < 4; i++) {
            int gr = row0 + 4 * ty + i;
            if (gr < M) {
                float4 o = make_float4(acc[i][0] + bb.x, acc[i][1] + bb.y,
                                       acc[i][2] + bb.z, acc[i][3] + bb.w);
                ((float4*)Olv)[(size_t)gr * 8 + (tx - 8)] = o;
            }
        }
    }
}

// ---------------- launch ----------------
extern "C" void kernel_launch(void* const* d_in, const int* in_sizes, int n_in,
                              void* d_out, int out_size) {
    const float* x   = (const float*)d_in[0];
    const void*  ei  = d_in[1];
    const float* ew  = (const float*)d_in[2];
    const float* W1  = (const float*)d_in[3];
    const float* b1  = (const float*)d_in[4];
    const float* Wmu = (const float*)d_in[5];
    const float* bmu = (const float*)d_in[6];
    const float* Wlv = (const float*)d_in[7];
    const float* blv = (const float*)d_in[8];

    int N = in_sizes[0] / IN_DIM;
    int E = in_sizes[2];
    float* outp = (float*)d_out;
    float* Omu = outp;
    float* Olv = outp + (size_t)N * LAT;

    // scratch pointers
    float *d_xw, *d_h, *d_h2;
    cudaGetSymbolAddress((void**)&d_xw, g_xw);
    cudaGetSymbolAddress((void**)&d_h, g_h);
    cudaGetSymbolAddress((void**)&d_h2, g_h2);

    int nThreads = 256;
    int nbN = (N + nThreads - 1) / nThreads;
    int nbE = (E + nThreads - 1) / nThreads;
    int nbScan = (N + 1023) / 1024;

    k_detect<<<1, 32>>>((const int*)ei);
    k_init<<<nbN, nThreads>>>(N);
    k_count<<<nbE, nThreads>>>(ei, ew, E);
    k_dinv<<<nbN, nThreads>>>(N);
    k_scan1<<<nbScan, 1024>>>(N);
    k_scan2<<<1, 32>>>(nbScan);
    k_scan3<<<nbN, nThreads>>>(N);
    k_fill<<<nbE, nThreads>>>(ei, ew, E);

    // layer 1: xw = x @ W1 ; h = relu(P xw + b1)
    int nbG = (N + 63) / 64;
    k_gemm1<<<nbG, 256>>>(x, W1, d_xw, N);
    int nbP = (N + 7) / 8;  // 8 warps per 256-thread block
    k_prop<<<nbP, 256>>>(d_xw, d_h, b1, 1, N);

    // layer 2+3 share one propagation: h2 = P h ; [mu|lv] = h2 @ [Wmu|Wlv] + b
    k_prop<<<nbP, 256>>>(d_h, d_h2, nullptr, 0, N);
    k_gemm2<<<nbG, 256>>>(d_h2, Wmu, Wlv, bmu, blv, Omu, Olv, N);
}